// round 15
// baseline (speedup 1.0000x reference)
#include <cuda_runtime.h>
#include <math.h>

#define OWN_DIM 7
#define INTR_DIM 5
#define N_HEADS 3
#define HEAD_DIM 5
#define N_INTR 256
#define HID 256
#define BATCH 16384
#define OBS_DIM 1287           // OWN_DIM + N_INTR*INTR_DIM
#define XDIM 22                // OWN_DIM + N_HEADS*HEAD_DIM
#define RPB 4                  // rows per attention block (2 warps per row)
#define TR 32                  // rows per MLP block
#define HPAD 36                // padded row length for h tile (144B, 16B-aligned)
#define KT 8                   // W2 k-rows per cp.async tile
#define NT (HID / KT)          // 32 tiles

// chunked overlap: 4 chunks of 4096 rows
#define NCHUNK 4
#define ROWS_PER_CHUNK (BATCH / NCHUNK)            // 4096
#define ABLK (ROWS_PER_CHUNK / RPB)                // 1024 attn blocks / chunk
#define MBLK (ROWS_PER_CHUNK / TR)                 // 128 mlp blocks / chunk

typedef unsigned long long u64;

// transposed x buffer: [feature][row]  (1.44 MB device-global scratch)
__device__ float g_xT[XDIM * BATCH];
// per-chunk completion counters (zeroed via cudaMemsetAsync each launch)
__device__ unsigned g_cnt[NCHUNK];

// ---- packed f32x2 helpers (sm_103a FFMA2 via PTX) ----
__device__ __forceinline__ u64 pack2(float lo, float hi){
    u64 r; asm("mov.b64 %0, {%1,%2};" : "=l"(r) : "f"(lo), "f"(hi)); return r;
}
__device__ __forceinline__ void unpack2(u64 v, float& lo, float& hi){
    asm("mov.b64 {%0,%1}, %2;" : "=f"(lo), "=f"(hi) : "l"(v));
}
__device__ __forceinline__ u64 ffma2(u64 a, u64 b, u64 c){
    u64 d; asm("fma.rn.f32x2 %0, %1, %2, %3;" : "=l"(d) : "l"(a), "l"(b), "l"(c)); return d;
}

// ---- cp.async helpers ----
__device__ __forceinline__ void cp16(float* s, const float* g){
    unsigned sa = (unsigned)__cvta_generic_to_shared(s);
    asm volatile("cp.async.cg.shared.global [%0], [%1], 16;" :: "r"(sa), "l"(g) : "memory");
}
#define CP_COMMIT() asm volatile("cp.async.commit_group;" ::: "memory")
#define CP_WAIT1()  asm volatile("cp.async.wait_group 1;" ::: "memory")

// hardware tanh: single MUFU.TANH (sm_75+)
__device__ __forceinline__ float tanh_hw(float x){
    float y; asm("tanh.approx.f32 %0, %1;" : "=f"(y) : "f"(x)); return y;
}

// L2 (non-L1) load — mlp reads of g_xT must not hit stale same-kernel L1
__device__ __forceinline__ float ldcg(const float* p){ return __ldcg(p); }

// ============================================================
// attention body: 2 warps per row, RPB=4 rows per block (R13 logic)
// ============================================================
__device__ __forceinline__ void attn_body(
    float* sm, int chunk, int bidx,
    const float* __restrict__ obs,
    const float* __restrict__ Wq, const float* __restrict__ bq,
    const float* __restrict__ Wk, const float* __restrict__ bk,
    const float* __restrict__ Wv, const float* __restrict__ bv,
    const float* __restrict__ v_att, const float* __restrict__ temp)
{
    // carve attn layout from dynamic smem (22.6KB of 56KB)
    float* s_obs = sm;                         // [RPB][OBS_DIM+1]
    float* s_w   = s_obs + RPB * (OBS_DIM + 1);// [316]
    float* s_red = s_w + 316;                  // [8][8]
    float* s_xb  = s_red + 64;                 // [8][16]
    const int WQ = 0, BQ = 105, WK = 120, BK = 195, WV = 210, BV = 285, VA = 300, TT = 315;

    const int tid  = threadIdx.x;
    const int w    = tid >> 5;
    const int lane = tid & 31;
    const int rloc = w >> 1;
    const int half = w & 1;

    if (tid < 105)      s_w[WQ + tid]        = Wq[tid];
    else if (tid < 120) s_w[BQ + tid - 105]  = bq[tid - 105];
    else if (tid < 195) s_w[WK + tid - 120]  = Wk[tid - 120];
    else if (tid < 210) s_w[BK + tid - 195]  = bk[tid - 195];
    if (tid < 75)       s_w[WV + tid]        = Wv[tid];
    else if (tid < 90)  s_w[BV + tid - 75]   = bv[tid - 75];
    else if (tid < 105) s_w[VA + tid - 90]   = v_att[tid - 90];
    if (tid == 255)     s_w[TT]              = fabsf(temp[0]);

    const int row = chunk * ROWS_PER_CHUNK + bidx * RPB + rloc;
    float* srow = s_obs + rloc * (OBS_DIM + 1);
    const float* gobs = obs + (size_t)row * OBS_DIM;
    for (int j = half * 32 + lane; j < OBS_DIM; j += 64) srow[j] = gobs[j];
    __syncthreads();

    const float* R = srow;

    u64 xi2[2][5];
    unsigned padmask = 0;
    #pragma unroll
    for (int p = 0; p < 2; p++){
        float a5[5], b5[5];
        {
            const float* pa = R + OWN_DIM + 5 * (half * 128 + lane + 32 * (2*p));
            float s = 0.f;
            #pragma unroll
            for (int i = 0; i < 5; i++){ a5[i] = pa[i]; s += fabsf(a5[i]); }
            if (s < 1e-6f) padmask |= (1u << (2*p));
        }
        {
            const float* pb = R + OWN_DIM + 5 * (half * 128 + lane + 32 * (2*p+1));
            float s = 0.f;
            #pragma unroll
            for (int i = 0; i < 5; i++){ b5[i] = pb[i]; s += fabsf(b5[i]); }
            if (s < 1e-6f) padmask |= (1u << (2*p+1));
        }
        #pragma unroll
        for (int i = 0; i < 5; i++) xi2[p][i] = pack2(a5[i], b5[i]);
    }

    // pass 1: scores
    const float T = s_w[TT];
    u64 sc2[3][2];
    #pragma unroll
    for (int h = 0; h < 3; h++){
        float qb[5];
        #pragma unroll
        for (int d = 0; d < 5; d++){
            float a = s_w[BQ + h*5 + d] + s_w[BK + h*5 + d];
            #pragma unroll
            for (int o = 0; o < 7; o++) a += s_w[WQ + (h*5 + d)*7 + o] * R[o];
            qb[d] = a;
        }
        #pragma unroll
        for (int p = 0; p < 2; p++) sc2[h][p] = pack2(0.f, 0.f);

        #pragma unroll
        for (int d = 0; d < 5; d++){
            const int rowk = (h*5 + d)*5;
            u64 w0 = pack2(s_w[WK + rowk + 0], s_w[WK + rowk + 0]);
            u64 w1 = pack2(s_w[WK + rowk + 1], s_w[WK + rowk + 1]);
            u64 w2 = pack2(s_w[WK + rowk + 2], s_w[WK + rowk + 2]);
            u64 w3 = pack2(s_w[WK + rowk + 3], s_w[WK + rowk + 3]);
            u64 w4 = pack2(s_w[WK + rowk + 4], s_w[WK + rowk + 4]);
            u64 q2 = pack2(qb[d], qb[d]);
            float va = s_w[VA + h*5 + d] * T;
            u64 va2 = pack2(va, va);
            #pragma unroll
            for (int p = 0; p < 2; p++){
                u64 kv = ffma2(xi2[p][0], w0, q2);
                kv = ffma2(xi2[p][1], w1, kv);
                kv = ffma2(xi2[p][2], w2, kv);
                kv = ffma2(xi2[p][3], w3, kv);
                kv = ffma2(xi2[p][4], w4, kv);
                float lo, hi; unpack2(kv, lo, hi);
                u64 e2 = pack2(tanh_hw(lo), tanh_hw(hi));
                sc2[h][p] = ffma2(e2, va2, sc2[h][p]);
            }
        }
    }

    // softmax across warp pair
    float s8[3][4];
    #pragma unroll
    for (int h = 0; h < 3; h++){
        #pragma unroll
        for (int p = 0; p < 2; p++){
            float lo, hi; unpack2(sc2[h][p], lo, hi);
            s8[h][2*p]   = ((padmask >> (2*p))   & 1u) ? -INFINITY : lo;
            s8[h][2*p+1] = ((padmask >> (2*p+1)) & 1u) ? -INFINITY : hi;
        }
        float m = fmaxf(fmaxf(s8[h][0], s8[h][1]), fmaxf(s8[h][2], s8[h][3]));
        #pragma unroll
        for (int off = 16; off; off >>= 1) m = fmaxf(m, __shfl_xor_sync(0xffffffffu, m, off));
        if (lane == 0) s_red[w * 8 + h] = m;
    }
    __syncthreads();

    float inv[3];
    #pragma unroll
    for (int h = 0; h < 3; h++){
        const float m = fmaxf(s_red[w * 8 + h], s_red[(w ^ 1) * 8 + h]);
        const bool ok = (m > -INFINITY);
        float l = 0.f;
        #pragma unroll
        for (int t = 0; t < 4; t++){
            float pr = ok ? __expf(s8[h][t] - m) : 0.f;
            s8[h][t] = pr;
            l += pr;
        }
        #pragma unroll
        for (int off = 16; off; off >>= 1) l += __shfl_xor_sync(0xffffffffu, l, off);
        if (lane == 0) s_red[w * 8 + 3 + h] = l;
        #pragma unroll
        for (int p = 0; p < 2; p++) sc2[h][p] = pack2(s8[h][2*p], s8[h][2*p+1]);
    }
    __syncthreads();
    #pragma unroll
    for (int h = 0; h < 3; h++){
        const float l = s_red[w * 8 + 3 + h] + s_red[(w ^ 1) * 8 + 3 + h];
        inv[h] = (l > 0.f) ? __fdividef(1.f, l) : 0.f;
    }

    // pass 2: xbar partials
    #pragma unroll
    for (int h = 0; h < 3; h++){
        u64 xh2[5];
        #pragma unroll
        for (int i = 0; i < 5; i++) xh2[i] = pack2(0.f, 0.f);
        #pragma unroll
        for (int p = 0; p < 2; p++){
            const u64 pr = sc2[h][p];
            #pragma unroll
            for (int i = 0; i < 5; i++) xh2[i] = ffma2(pr, xi2[p][i], xh2[i]);
        }
        float xh[5];
        #pragma unroll
        for (int i = 0; i < 5; i++){
            float lo, hi; unpack2(xh2[i], lo, hi);
            float c = lo + hi;
            #pragma unroll
            for (int off = 16; off; off >>= 1) c += __shfl_xor_sync(0xffffffffu, c, off);
            xh[i] = c;
        }
        if (lane < 5) s_xb[w * 16 + h*5 + lane] = xh[lane];
    }
    __syncthreads();

    if (half == 0){
        if (lane < 15){
            const int h = lane / 5;
            float c = s_w[BV + lane] * ((inv[h] > 0.f) ? 1.f : 0.f);
            #pragma unroll
            for (int i = 0; i < 5; i++){
                const float xb = (s_xb[w * 16 + h*5 + i] + s_xb[(w + 1) * 16 + h*5 + i]) * inv[h];
                c += s_w[WV + lane*5 + i] * xb;
            }
            g_xT[(7 + lane) * BATCH + row] = c;
        } else if (lane < 22){
            g_xT[(lane - 15) * BATCH + row] = R[lane - 15];
        }
    }

    // signal chunk completion (release)
    __syncthreads();
    if (tid == 0){
        __threadfence();
        atomicAdd(&g_cnt[chunk], 1u);
    }
}

// ============================================================
// MLP body (R13 logic; g_xT read via ld.cg; waits on chunk counter)
// ============================================================
__device__ __forceinline__ void mlp_body(
    float* sm, int chunk, int bidx,
    const float* __restrict__ W1, const float* __restrict__ b1,
    const float* __restrict__ W2, const float* __restrict__ b2,
    const float* __restrict__ Wf, const float* __restrict__ bf,
    const float* __restrict__ log_std, float* __restrict__ out)
{
    float* xsT  = sm;                       // [XDIM][TR]   704 floats
    float* hT   = sm + XDIM * TR;           // [HID][HPAD]  9216 floats
    float* wbuf = hT + HID * HPAD;          // [2][KT*HID]  4096 floats

    const int tid   = threadIdx.x;
    const int wid   = tid >> 5;
    const int lane  = tid & 31;
    const int r0    = (lane & 7) * 4;
    const int c0    = wid * 32 + (lane >> 3) * 8;
    const int rbase = chunk * ROWS_PER_CHUNK + bidx * TR;

    // acquire-wait for this chunk's attention blocks
    if (tid == 0){
        unsigned v;
        do {
            asm volatile("ld.acquire.gpu.global.u32 %0, [%1];"
                         : "=r"(v) : "l"(&g_cnt[chunk]) : "memory");
            if (v < (unsigned)ABLK) __nanosleep(128);
        } while (v < (unsigned)ABLK);
    }
    __syncthreads();

    // load x transposed tile via L2 (bypass possibly-stale L1)
    for (int idx = tid; idx < XDIM * TR; idx += 256)
        xsT[idx] = ldcg(&g_xT[(idx >> 5) * BATCH + rbase + (idx & 31)]);
    __syncthreads();

    // ---- stage 1 ----
    {
        u64 acc[8][2];
        {
            const float4 ba = *(const float4*)(b1 + c0);
            const float4 bb = *(const float4*)(b1 + c0 + 4);
            float bv8[8] = {ba.x, ba.y, ba.z, ba.w, bb.x, bb.y, bb.z, bb.w};
            #pragma unroll
            for (int c = 0; c < 8; c++){ acc[c][0] = pack2(bv8[c], bv8[c]); acc[c][1] = acc[c][0]; }
        }
        #pragma unroll 2
        for (int i = 0; i < XDIM; i++){
            const float4 wa = *(const float4*)(W1 + i * HID + c0);
            const float4 wb = *(const float4*)(W1 + i * HID + c0 + 4);
            const ulonglong2 xx = *(const ulonglong2*)(xsT + i * TR + r0);
            float wv[8] = {wa.x, wa.y, wa.z, wa.w, wb.x, wb.y, wb.z, wb.w};
            #pragma unroll
            for (int c = 0; c < 8; c++){
                const u64 wp = pack2(wv[c], wv[c]);
                acc[c][0] = ffma2(xx.x, wp, acc[c][0]);
                acc[c][1] = ffma2(xx.y, wp, acc[c][1]);
            }
        }
        #pragma unroll
        for (int c = 0; c < 8; c++){
            float a0, a1, a2, a3;
            unpack2(acc[c][0], a0, a1);
            unpack2(acc[c][1], a2, a3);
            a0 = fmaxf(a0, 0.2f * a0); a1 = fmaxf(a1, 0.2f * a1);
            a2 = fmaxf(a2, 0.2f * a2); a3 = fmaxf(a3, 0.2f * a3);
            *(float4*)(hT + (c0 + c) * HPAD + r0) = make_float4(a0, a1, a2, a3);
        }
    }
    __syncthreads();

    // ---- stage 2: cp.async double-buffered W2 ----
    {
        #pragma unroll
        for (int t = 0; t < 2; t++){
            float* dst = wbuf + t * (KT * HID);
            const float* src = W2 + t * (KT * HID);
            cp16(dst + tid * 4,        src + tid * 4);
            cp16(dst + 1024 + tid * 4, src + 1024 + tid * 4);
            CP_COMMIT();
        }

        u64 acc[8][2];
        {
            const float4 ba = *(const float4*)(b2 + c0);
            const float4 bb = *(const float4*)(b2 + c0 + 4);
            float bv8[8] = {ba.x, ba.y, ba.z, ba.w, bb.x, bb.y, bb.z, bb.w};
            #pragma unroll
            for (int c = 0; c < 8; c++){ acc[c][0] = pack2(bv8[c], bv8[c]); acc[c][1] = acc[c][0]; }
        }

        for (int kt = 0; kt < NT; kt++){
            CP_WAIT1();
            __syncthreads();
            const float* wb = wbuf + (kt & 1) * (KT * HID);
            #pragma unroll
            for (int ii = 0; ii < KT; ii++){
                const float4 wva = *(const float4*)(wb + ii * HID + c0);
                const float4 wvb = *(const float4*)(wb + ii * HID + c0 + 4);
                const ulonglong2 xx = *(const ulonglong2*)(hT + (kt * KT + ii) * HPAD + r0);
                float wv[8] = {wva.x, wva.y, wva.z, wva.w, wvb.x, wvb.y, wvb.z, wvb.w};
                #pragma unroll
                for (int c = 0; c < 8; c++){
                    const u64 wp = pack2(wv[c], wv[c]);
                    acc[c][0] = ffma2(xx.x, wp, acc[c][0]);
                    acc[c][1] = ffma2(xx.y, wp, acc[c][1]);
                }
            }
            __syncthreads();
            if (kt + 2 < NT){
                float* dst = wbuf + (kt & 1) * (KT * HID);
                const float* src = W2 + (kt + 2) * (KT * HID);
                cp16(dst + tid * 4,        src + tid * 4);
                cp16(dst + 1024 + tid * 4, src + 1024 + tid * 4);
            }
            CP_COMMIT();
        }

        #pragma unroll
        for (int c = 0; c < 8; c++){
            float a0, a1, a2, a3;
            unpack2(acc[c][0], a0, a1);
            unpack2(acc[c][1], a2, a3);
            a0 = fmaxf(a0, 0.2f * a0); a1 = fmaxf(a1, 0.2f * a1);
            a2 = fmaxf(a2, 0.2f * a2); a3 = fmaxf(a3, 0.2f * a3);
            *(float4*)(hT + (c0 + c) * HPAD + r0) = make_float4(a0, a1, a2, a3);
        }
    }
    __syncthreads();

    // ---- stage 3 ----
    {
        const int r  = tid >> 3;
        const int a  = (tid >> 2) & 1;
        const int jc = tid & 3;
        float p = 0.f;
        const int j0 = jc * 64;
        #pragma unroll 8
        for (int j = j0; j < j0 + 64; j++)
            p += hT[j * HPAD + r] * Wf[j * 2 + a];
        xsT[tid] = p;
    }
    __syncthreads();
    if (tid < 64){
        const int r = tid >> 1, a = tid & 1;
        float acc = bf[a];
        #pragma unroll
        for (int q = 0; q < 4; q++) acc += xsT[r * 8 + a * 4 + q];
        const int row = rbase + r;
        out[row * 4 + a]     = acc;
        out[row * 4 + 2 + a] = log_std[a];
    }
}

// ============================================================
// Fused kernel: block-id layout interleaves attn chunks with lagged mlp chunks
//   [A0·1024][A1·1024][M0·128][A2·1024][M1·128][A3·1024][M2·128][M3·128]
// Each M chunk is scheduled a full attn-chunk after its dependency -> ~0 spin.
// ============================================================
__global__ void __launch_bounds__(256, 3)
fused_kernel(const float* __restrict__ obs,
             const float* __restrict__ Wq, const float* __restrict__ bq,
             const float* __restrict__ Wk, const float* __restrict__ bk,
             const float* __restrict__ Wv, const float* __restrict__ bv,
             const float* __restrict__ v_att, const float* __restrict__ temp,
             const float* __restrict__ W1, const float* __restrict__ b1,
             const float* __restrict__ W2, const float* __restrict__ b2,
             const float* __restrict__ Wf, const float* __restrict__ bf,
             const float* __restrict__ log_std, float* __restrict__ out)
{
    extern __shared__ float sm[];
    const int bid = blockIdx.x;

    int chunk, idx;
    bool is_mlp;
    if      (bid < 1024){ chunk = 0; idx = bid;        is_mlp = false; }
    else if (bid < 2048){ chunk = 1; idx = bid - 1024; is_mlp = false; }
    else if (bid < 2176){ chunk = 0; idx = bid - 2048; is_mlp = true;  }
    else if (bid < 3200){ chunk = 2; idx = bid - 2176; is_mlp = false; }
    else if (bid < 3328){ chunk = 1; idx = bid - 3200; is_mlp = true;  }
    else if (bid < 4352){ chunk = 3; idx = bid - 3328; is_mlp = false; }
    else if (bid < 4480){ chunk = 2; idx = bid - 4352; is_mlp = true;  }
    else                { chunk = 3; idx = bid - 4480; is_mlp = true;  }

    if (!is_mlp)
        attn_body(sm, chunk, idx, obs, Wq, bq, Wk, bk, Wv, bv, v_att, temp);
    else
        mlp_body(sm, chunk, idx, W1, b1, W2, b2, Wf, bf, log_std, out);
}

// ============================================================
extern "C" void kernel_launch(void* const* d_in, const int* in_sizes, int n_in,
                              void* d_out, int out_size)
{
    const float* obs     = (const float*)d_in[0];
    const float* Wq      = (const float*)d_in[1];
    const float* bq      = (const float*)d_in[2];
    const float* Wk      = (const float*)d_in[3];
    const float* bk      = (const float*)d_in[4];
    const float* Wv      = (const float*)d_in[5];
    const float* bv      = (const float*)d_in[6];
    const float* v_att   = (const float*)d_in[7];
    const float* temp    = (const float*)d_in[8];
    const float* W1      = (const float*)d_in[9];
    const float* b1      = (const float*)d_in[10];
    const float* W2      = (const float*)d_in[11];
    const float* b2      = (const float*)d_in[12];
    const float* Wf      = (const float*)d_in[13];
    const float* bf      = (const float*)d_in[14];
    const float* log_std = (const float*)d_in[15];

    // zero chunk counters (graph-capturable, no alloc)
    void* cnt_ptr = nullptr;
    cudaGetSymbolAddress(&cnt_ptr, g_cnt);
    cudaMemsetAsync(cnt_ptr, 0, NCHUNK * sizeof(unsigned));

    const size_t smem = (size_t)(XDIM * TR + HID * HPAD + 2 * KT * HID) * sizeof(float);  // 56064 B
    cudaFuncSetAttribute(fused_kernel, cudaFuncAttributeMaxDynamicSharedMemorySize, (int)smem);

    const int nblocks = NCHUNK * ABLK + NCHUNK * MBLK;  // 4608
    fused_kernel<<<nblocks, 256, smem>>>(obs, Wq, bq, Wk, bk, Wv, bv, v_att, temp,
                                         W1, b1, W2, b2, Wf, bf, log_std, (float*)d_out);
}

// round 16
// speedup vs baseline: 1.1379x; 1.1379x over previous
#include <cuda_runtime.h>
#include <math.h>

#define OWN_DIM 7
#define INTR_DIM 5
#define N_HEADS 3
#define HEAD_DIM 5
#define N_INTR 256
#define HID 256
#define BATCH 16384
#define OBS_DIM 1287           // OWN_DIM + N_INTR*INTR_DIM
#define XDIM 22                // OWN_DIM + N_HEADS*HEAD_DIM
#define RPB 4                  // rows per attention block (2 warps per row)
#define TR 32                  // rows per MLP block
#define HPAD 36                // padded row length for h tile (144B, 16B-aligned)
#define KT 8                   // W2 k-rows per cp.async tile
#define NT (HID / KT)          // 32 tiles

typedef unsigned long long u64;

// transposed x buffer: [feature][row]  (1.44 MB device-global scratch)
__device__ float g_xT[XDIM * BATCH];

// ---- packed f32x2 helpers (sm_103a FFMA2 via PTX) ----
__device__ __forceinline__ u64 pack2(float lo, float hi){
    u64 r; asm("mov.b64 %0, {%1,%2};" : "=l"(r) : "f"(lo), "f"(hi)); return r;
}
__device__ __forceinline__ void unpack2(u64 v, float& lo, float& hi){
    asm("mov.b64 {%0,%1}, %2;" : "=f"(lo), "=f"(hi) : "l"(v));
}
__device__ __forceinline__ u64 ffma2(u64 a, u64 b, u64 c){
    u64 d; asm("fma.rn.f32x2 %0, %1, %2, %3;" : "=l"(d) : "l"(a), "l"(b), "l"(c)); return d;
}

// ---- cp.async helpers ----
__device__ __forceinline__ void cp16(float* s, const float* g){
    unsigned sa = (unsigned)__cvta_generic_to_shared(s);
    asm volatile("cp.async.cg.shared.global [%0], [%1], 16;" :: "r"(sa), "l"(g) : "memory");
}
#define CP_COMMIT() asm volatile("cp.async.commit_group;" ::: "memory")
#define CP_WAIT1()  asm volatile("cp.async.wait_group 1;" ::: "memory")

// hardware tanh: single MUFU.TANH (sm_75+)
__device__ __forceinline__ float tanh_hw(float x){
    float y; asm("tanh.approx.f32 %0, %1;" : "=f"(y) : "f"(x)); return y;
}

// ============================================================
// Kernel 1: attention.  2 warps per row, RPB=4 rows/block.
// R15 changes: no s_obs staging (direct gmem item loads + own[] in regs),
// q computed ONCE per row by 15 lanes into s_q (was 105 LDS+105 FFMA per
// thread), s_w shrunk to the 181 floats needed after the barrier.
// ============================================================
__global__ void __launch_bounds__(256, 3)
attn_kernel(const float* __restrict__ obs,
            const float* __restrict__ Wq, const float* __restrict__ bq,
            const float* __restrict__ Wk, const float* __restrict__ bk,
            const float* __restrict__ Wv, const float* __restrict__ bv,
            const float* __restrict__ v_att, const float* __restrict__ temp)
{
    __shared__ float s_w[181];       // WK@0 (75), WV@75 (75), BV@150 (15), VA@165 (15), T@180
    __shared__ float s_q[RPB][16];   // per-row q + bq + bk (15 used)
    __shared__ float s_red[8][8];    // [warp][0..2]=m_h, [3..5]=l_h
    __shared__ float s_xb[8][16];    // [warp][15 xbar partials]
    const int WKo = 0, WVo = 75, BVo = 150, VAo = 165, TTo = 180;

    const int tid  = threadIdx.x;
    const int w    = tid >> 5;
    const int lane = tid & 31;
    const int rloc = w >> 1;          // local row 0..3
    const int half = w & 1;           // item half

    // stage the weights needed after the barrier
    if (tid < 75)        s_w[WKo + tid]       = Wk[tid];
    else if (tid < 150)  s_w[WVo + tid - 75]  = Wv[tid - 75];
    else if (tid < 165)  s_w[BVo + tid - 150] = bv[tid - 150];
    else if (tid < 180)  s_w[VAo + tid - 165] = v_att[tid - 165];
    else if (tid == 180) s_w[TTo]             = fabsf(temp[0]);

    const int row = blockIdx.x * RPB + rloc;
    const float* gobs = obs + (size_t)row * OBS_DIM;

    // own features: registers (broadcast LDG, dedupes across the warp)
    float own[7];
    #pragma unroll
    for (int o = 0; o < 7; o++) own[o] = __ldg(gobs + o);

    // q computed once per row: even warp, lanes 0..14 -> s_q[rloc][hd]
    if (half == 0 && lane < 15){
        float a = __ldg(bq + lane) + __ldg(bk + lane);
        #pragma unroll
        for (int o = 0; o < 7; o++) a += __ldg(Wq + lane * 7 + o) * own[o];
        s_q[rloc][lane] = a;
    }

    // items loaded DIRECTLY from gmem (no smem staging)
    // lane owns items n = half*128 + lane + 32*t, packed pairs p=(t=2p,2p+1)
    u64 xi2[2][5];
    unsigned padmask = 0;
    #pragma unroll
    for (int p = 0; p < 2; p++){
        const float* pa = gobs + OWN_DIM + 5 * (half * 128 + lane + 64 * p);
        const float* pb = pa + 160;   // +32 items * 5
        float a5[5], b5[5];
        float sa = 0.f, sb = 0.f;
        #pragma unroll
        for (int i = 0; i < 5; i++){ a5[i] = __ldg(pa + i); sa += fabsf(a5[i]); }
        #pragma unroll
        for (int i = 0; i < 5; i++){ b5[i] = __ldg(pb + i); sb += fabsf(b5[i]); }
        if (sa < 1e-6f) padmask |= (1u << (2*p));
        if (sb < 1e-6f) padmask |= (1u << (2*p+1));
        #pragma unroll
        for (int i = 0; i < 5; i++) xi2[p][i] = pack2(a5[i], b5[i]);
    }
    __syncthreads();                  // s_w + s_q ready

    // -------- pass 1: scores (T folded into v_att) --------
    const float T = s_w[TTo];
    u64 sc2[3][2];
    #pragma unroll
    for (int h = 0; h < 3; h++){
        #pragma unroll
        for (int p = 0; p < 2; p++) sc2[h][p] = pack2(0.f, 0.f);
        #pragma unroll
        for (int d = 0; d < 5; d++){
            const int hd = h*5 + d;
            const int rowk = hd * 5;
            u64 w0 = pack2(s_w[WKo + rowk + 0], s_w[WKo + rowk + 0]);
            u64 w1 = pack2(s_w[WKo + rowk + 1], s_w[WKo + rowk + 1]);
            u64 w2 = pack2(s_w[WKo + rowk + 2], s_w[WKo + rowk + 2]);
            u64 w3 = pack2(s_w[WKo + rowk + 3], s_w[WKo + rowk + 3]);
            u64 w4 = pack2(s_w[WKo + rowk + 4], s_w[WKo + rowk + 4]);
            const float qv = s_q[rloc][hd];
            u64 q2 = pack2(qv, qv);
            float va = s_w[VAo + hd] * T;
            u64 va2 = pack2(va, va);
            #pragma unroll
            for (int p = 0; p < 2; p++){
                u64 kv = ffma2(xi2[p][0], w0, q2);
                kv = ffma2(xi2[p][1], w1, kv);
                kv = ffma2(xi2[p][2], w2, kv);
                kv = ffma2(xi2[p][3], w3, kv);
                kv = ffma2(xi2[p][4], w4, kv);
                float lo, hi; unpack2(kv, lo, hi);
                u64 e2 = pack2(tanh_hw(lo), tanh_hw(hi));
                sc2[h][p] = ffma2(e2, va2, sc2[h][p]);
            }
        }
    }

    // -------- softmax: warp-local then cross-warp (pair) combine --------
    float s8[3][4];
    #pragma unroll
    for (int h = 0; h < 3; h++){
        #pragma unroll
        for (int p = 0; p < 2; p++){
            float lo, hi; unpack2(sc2[h][p], lo, hi);
            s8[h][2*p]   = ((padmask >> (2*p))   & 1u) ? -INFINITY : lo;
            s8[h][2*p+1] = ((padmask >> (2*p+1)) & 1u) ? -INFINITY : hi;
        }
        float m = fmaxf(fmaxf(s8[h][0], s8[h][1]), fmaxf(s8[h][2], s8[h][3]));
        #pragma unroll
        for (int off = 16; off; off >>= 1) m = fmaxf(m, __shfl_xor_sync(0xffffffffu, m, off));
        if (lane == 0) s_red[w][h] = m;
    }
    __syncthreads();

    float inv[3];
    #pragma unroll
    for (int h = 0; h < 3; h++){
        const float m = fmaxf(s_red[w][h], s_red[w ^ 1][h]);
        const bool ok = (m > -INFINITY);
        float l = 0.f;
        #pragma unroll
        for (int t = 0; t < 4; t++){
            float pr = ok ? __expf(s8[h][t] - m) : 0.f;
            s8[h][t] = pr;
            l += pr;
        }
        #pragma unroll
        for (int off = 16; off; off >>= 1) l += __shfl_xor_sync(0xffffffffu, l, off);
        if (lane == 0) s_red[w][3 + h] = l;
        #pragma unroll
        for (int p = 0; p < 2; p++) sc2[h][p] = pack2(s8[h][2*p], s8[h][2*p+1]);
    }
    __syncthreads();
    #pragma unroll
    for (int h = 0; h < 3; h++){
        const float l = s_red[w][3 + h] + s_red[w ^ 1][3 + h];
        inv[h] = (l > 0.f) ? __fdividef(1.f, l) : 0.f;
    }

    // -------- pass 2: per-head xbar partial = sum alpha*x over this half --------
    #pragma unroll
    for (int h = 0; h < 3; h++){
        u64 xh2[5];
        #pragma unroll
        for (int i = 0; i < 5; i++) xh2[i] = pack2(0.f, 0.f);
        #pragma unroll
        for (int p = 0; p < 2; p++){
            const u64 pr = sc2[h][p];
            #pragma unroll
            for (int i = 0; i < 5; i++) xh2[i] = ffma2(pr, xi2[p][i], xh2[i]);
        }
        float xh[5];
        #pragma unroll
        for (int i = 0; i < 5; i++){
            float lo, hi; unpack2(xh2[i], lo, hi);
            float c = lo + hi;
            #pragma unroll
            for (int off = 16; off; off >>= 1) c += __shfl_xor_sync(0xffffffffu, c, off);
            xh[i] = c;
        }
        if (lane < 5) s_xb[w][h*5 + lane] = xh[lane];
    }
    __syncthreads();

    // -------- combine halves & emit (one warp per row) --------
    if (half == 0){
        if (lane < 15){
            const int h = lane / 5;
            float c = s_w[BVo + lane] * ((inv[h] > 0.f) ? 1.f : 0.f);
            #pragma unroll
            for (int i = 0; i < 5; i++){
                const float xb = (s_xb[w][h*5 + i] + s_xb[w + 1][h*5 + i]) * inv[h];
                c += s_w[WVo + lane*5 + i] * xb;
            }
            g_xT[(7 + lane) * BATCH + row] = c;
        } else if (lane < 22){
            const int o = lane - 15;
            float v = own[0];
            #pragma unroll
            for (int oo = 1; oo < 7; oo++) v = (o == oo) ? own[oo] : v;
            g_xT[o * BATCH + row] = v;
        }
    }
}

// ============================================================
// Kernel 2: MLP.  (byte-identical to R13 best: ~62us)
// TR=32 rows/block, register-tiled 4x8; block-wide cp.async double-buffered
// W2 tiles; 56 KB smem, <=64 regs -> 4 blocks/SM -> grid 512 in ONE wave.
// ============================================================
__global__ void __launch_bounds__(256, 4)
mlp_kernel(const float* __restrict__ W1, const float* __restrict__ b1,
           const float* __restrict__ W2, const float* __restrict__ b2,
           const float* __restrict__ Wf, const float* __restrict__ bf,
           const float* __restrict__ log_std, float* __restrict__ out)
{
    extern __shared__ float sm[];
    float* xsT  = sm;                       // [XDIM][TR]   704 floats (reused as reduce buf)
    float* hT   = sm + XDIM * TR;           // [HID][HPAD]  9216 floats (h1, then h2)
    float* wbuf = hT + HID * HPAD;          // [2][KT*HID]  4096 floats

    const int tid   = threadIdx.x;
    const int wid   = tid >> 5;
    const int lane  = tid & 31;
    const int r0    = (lane & 7) * 4;            // rows r0..r0+3
    const int c0    = wid * 32 + (lane >> 3) * 8; // cols c0..c0+7
    const int rbase = blockIdx.x * TR;

    // load x transposed tile (coalesced)
    for (int idx = tid; idx < XDIM * TR; idx += 256)
        xsT[idx] = g_xT[(idx >> 5) * BATCH + rbase + (idx & 31)];
    __syncthreads();

    // ---- stage 1: h1 = lrelu(x @ W1 + b1) ----
    {
        u64 acc[8][2];                       // [col][row-pair]
        {
            const float4 ba = *(const float4*)(b1 + c0);
            const float4 bb = *(const float4*)(b1 + c0 + 4);
            float bv8[8] = {ba.x, ba.y, ba.z, ba.w, bb.x, bb.y, bb.z, bb.w};
            #pragma unroll
            for (int c = 0; c < 8; c++){ acc[c][0] = pack2(bv8[c], bv8[c]); acc[c][1] = acc[c][0]; }
        }
        #pragma unroll 2
        for (int i = 0; i < XDIM; i++){
            const float4 wa = *(const float4*)(W1 + i * HID + c0);
            const float4 wb = *(const float4*)(W1 + i * HID + c0 + 4);
            const ulonglong2 xx = *(const ulonglong2*)(xsT + i * TR + r0);
            float wv[8] = {wa.x, wa.y, wa.z, wa.w, wb.x, wb.y, wb.z, wb.w};
            #pragma unroll
            for (int c = 0; c < 8; c++){
                const u64 wp = pack2(wv[c], wv[c]);
                acc[c][0] = ffma2(xx.x, wp, acc[c][0]);
                acc[c][1] = ffma2(xx.y, wp, acc[c][1]);
            }
        }
        #pragma unroll
        for (int c = 0; c < 8; c++){
            float a0, a1, a2, a3;
            unpack2(acc[c][0], a0, a1);
            unpack2(acc[c][1], a2, a3);
            a0 = fmaxf(a0, 0.2f * a0); a1 = fmaxf(a1, 0.2f * a1);
            a2 = fmaxf(a2, 0.2f * a2); a3 = fmaxf(a3, 0.2f * a3);
            *(float4*)(hT + (c0 + c) * HPAD + r0) = make_float4(a0, a1, a2, a3);
        }
    }
    __syncthreads();

    // ---- stage 2: h2 = lrelu(h1 @ W2 + b2), cp.async double-buffered weights ----
    {
        #pragma unroll
        for (int t = 0; t < 2; t++){
            float* dst = wbuf + t * (KT * HID);
            const float* src = W2 + t * (KT * HID);
            cp16(dst + tid * 4,        src + tid * 4);
            cp16(dst + 1024 + tid * 4, src + 1024 + tid * 4);
            CP_COMMIT();
        }

        u64 acc[8][2];
        {
            const float4 ba = *(const float4*)(b2 + c0);
            const float4 bb = *(const float4*)(b2 + c0 + 4);
            float bv8[8] = {ba.x, ba.y, ba.z, ba.w, bb.x, bb.y, bb.z, bb.w};
            #pragma unroll
            for (int c = 0; c < 8; c++){ acc[c][0] = pack2(bv8[c], bv8[c]); acc[c][1] = acc[c][0]; }
        }

        for (int kt = 0; kt < NT; kt++){
            CP_WAIT1();                      // tile kt resident
            __syncthreads();
            const float* wb = wbuf + (kt & 1) * (KT * HID);
            #pragma unroll
            for (int ii = 0; ii < KT; ii++){
                const float4 wva = *(const float4*)(wb + ii * HID + c0);
                const float4 wvb = *(const float4*)(wb + ii * HID + c0 + 4);
                const ulonglong2 xx = *(const ulonglong2*)(hT + (kt * KT + ii) * HPAD + r0);
                float wv[8] = {wva.x, wva.y, wva.z, wva.w, wvb.x, wvb.y, wvb.z, wvb.w};
                #pragma unroll
                for (int c = 0; c < 8; c++){
                    const u64 wp = pack2(wv[c], wv[c]);
                    acc[c][0] = ffma2(xx.x, wp, acc[c][0]);
                    acc[c][1] = ffma2(xx.y, wp, acc[c][1]);
                }
            }
            __syncthreads();                 // all reads of this buffer done
            if (kt + 2 < NT){
                float* dst = wbuf + (kt & 1) * (KT * HID);
                const float* src = W2 + (kt + 2) * (KT * HID);
                cp16(dst + tid * 4,        src + tid * 4);
                cp16(dst + 1024 + tid * 4, src + 1024 + tid * 4);
            }
            CP_COMMIT();                     // empty group when no prefetch keeps WAIT1 exact
        }

        // write h2 over hT (all stage-2 reads completed at last barrier)
        #pragma unroll
        for (int c = 0; c < 8; c++){
            float a0, a1, a2, a3;
            unpack2(acc[c][0], a0, a1);
            unpack2(acc[c][1], a2, a3);
            a0 = fmaxf(a0, 0.2f * a0); a1 = fmaxf(a1, 0.2f * a1);
            a2 = fmaxf(a2, 0.2f * a2); a3 = fmaxf(a3, 0.2f * a3);
            *(float4*)(hT + (c0 + c) * HPAD + r0) = make_float4(a0, a1, a2, a3);
        }
    }
    __syncthreads();

    // ---- stage 3: out = h2 @ Wf + bf ; append log_std ----
    {
        const int r  = tid >> 3;
        const int a  = (tid >> 2) & 1;
        const int jc = tid & 3;
        float p = 0.f;
        const int j0 = jc * 64;
        #pragma unroll 8
        for (int j = j0; j < j0 + 64; j++)
            p += hT[j * HPAD + r] * Wf[j * 2 + a];
        xsT[tid] = p;                        // reuse xsT as reduce buffer
    }
    __syncthreads();
    if (tid < 64){
        const int r = tid >> 1, a = tid & 1;
        float acc = bf[a];
        #pragma unroll
        for (int q = 0; q < 4; q++) acc += xsT[r * 8 + a * 4 + q];
        const int row = rbase + r;
        out[row * 4 + a]     = acc;
        out[row * 4 + 2 + a] = log_std[a];
    }
}

// ============================================================
extern "C" void kernel_launch(void* const* d_in, const int* in_sizes, int n_in,
                              void* d_out, int out_size)
{
    const float* obs     = (const float*)d_in[0];
    const float* Wq      = (const float*)d_in[1];
    const float* bq      = (const float*)d_in[2];
    const float* Wk      = (const float*)d_in[3];
    const float* bk      = (const float*)d_in[4];
    const float* Wv      = (const float*)d_in[5];
    const float* bv      = (const float*)d_in[6];
    const float* v_att   = (const float*)d_in[7];
    const float* temp    = (const float*)d_in[8];
    const float* W1      = (const float*)d_in[9];
    const float* b1      = (const float*)d_in[10];
    const float* W2      = (const float*)d_in[11];
    const float* b2      = (const float*)d_in[12];
    const float* Wf      = (const float*)d_in[13];
    const float* bf      = (const float*)d_in[14];
    const float* log_std = (const float*)d_in[15];

    attn_kernel<<<BATCH / RPB, 256>>>(obs, Wq, bq, Wk, bk, Wv, bv, v_att, temp);

    const size_t smem = (size_t)(XDIM * TR + HID * HPAD + 2 * KT * HID) * sizeof(float);  // 56064 B
    cudaFuncSetAttribute(mlp_kernel, cudaFuncAttributeMaxDynamicSharedMemorySize, (int)smem);
    mlp_kernel<<<BATCH / TR, 256, smem>>>(W1, b1, W2, b2, Wf, bf, log_std, (float*)d_out);
}